// round 1
// baseline (speedup 1.0000x reference)
#include <cuda_runtime.h>
#include <cstdint>

#define BB    4
#define NPTS  4096
#define TPB   256
#define NPAIR (NPTS / 2)          // 2048 target pairs in smem
#define BPB   (NPTS / TPB)        // 16 query blocks per (batch, dir)
#define NBLOCKS (2 * BB * BPB)    // 128 blocks total

__device__ float g_partials[NBLOCKS];

__device__ __forceinline__ uint64_t pk2(float lo, float hi) {
    uint64_t r;
    asm("mov.b64 %0, {%1, %2};" : "=l"(r) : "f"(lo), "f"(hi));
    return r;
}

__device__ __forceinline__ uint64_t fma2(uint64_t a, uint64_t b, uint64_t c) {
    uint64_t d;
    asm("fma.rn.f32x2 %0, %1, %2, %3;" : "=l"(d) : "l"(a), "l"(b), "l"(c));
    return d;
}

// One block: 256 query points vs full 4096-point target set held in smem.
// Targets stored pair-interleaved so LDS.128 yields packed f32x2 operands:
//   sA[p] = {x0, x1, y0, y1}   sB[p] = {z0, z1, w0, w1}  (w = |t|^2)
__global__ void __launch_bounds__(TPB)
chamfer_kernel(const float* __restrict__ src, const float* __restrict__ tgt)
{
    extern __shared__ float4 sm[];
    float4* sA = sm;
    float4* sB = sm + NPAIR;

    int blk = blockIdx.x;
    int dir = blk / (BB * BPB);        // 0: source->target, 1: target->source
    int loc = blk % (BB * BPB);
    int b   = loc / BPB;
    int qb  = loc % BPB;

    const float* qbase = (dir == 0 ? src : tgt) + (size_t)b * NPTS * 3;
    const float* dbase = (dir == 0 ? tgt : src) + (size_t)b * NPTS * 3;

    // Stage target set into pair-interleaved smem, precompute |t|^2.
    for (int p = threadIdx.x; p < NPAIR; p += TPB) {
        const float* t = dbase + 6 * p;
        float x0 = t[0], y0 = t[1], z0 = t[2];
        float x1 = t[3], y1 = t[4], z1 = t[5];
        sA[p] = make_float4(x0, x1, y0, y1);
        sB[p] = make_float4(z0, z1,
                            fmaf(x0, x0, fmaf(y0, y0, z0 * z0)),
                            fmaf(x1, x1, fmaf(y1, y1, z1 * z1)));
    }
    __syncthreads();

    int q = qb * TPB + threadIdx.x;
    float sx = qbase[3 * q], sy = qbase[3 * q + 1], sz = qbase[3 * q + 2];
    float x2 = fmaf(sx, sx, fmaf(sy, sy, sz * sz));

    // Pre-scale source by -2: per target  v = (-2s)·t + |t|^2  -> 3 FFMA2 / 2 targets
    uint64_t S2X = pk2(-2.f * sx, -2.f * sx);
    uint64_t S2Y = pk2(-2.f * sy, -2.f * sy);
    uint64_t S2Z = pk2(-2.f * sz, -2.f * sz);

    const ulonglong2* A  = (const ulonglong2*)sA;   // .x = {x0,x1}, .y = {y0,y1}
    const ulonglong2* Bm = (const ulonglong2*)sB;   // .x = {z0,z1}, .y = {w0,w1}

    float m0 = 3.4e38f, m1 = 3.4e38f;
    #pragma unroll 8
    for (int p = 0; p < NPAIR; p++) {
        ulonglong2 a  = A[p];
        ulonglong2 bb = Bm[p];
        uint64_t v = fma2(S2X, a.x, fma2(S2Y, a.y, fma2(S2Z, bb.x, bb.y)));
        float v0, v1;
        asm("mov.b64 {%0, %1}, %2;" : "=f"(v0), "=f"(v1) : "l"(v));
        m0 = fminf(m0, v0);
        m1 = fminf(m1, v1);
    }
    float m = fminf(m0, m1) + x2;   // add |s|^2 after the min (constant shift)

    // Deterministic block reduction (reuse smem after sync).
    __syncthreads();
    float* red = (float*)sm;
    red[threadIdx.x] = m;
    __syncthreads();
    #pragma unroll
    for (int s = TPB / 2; s > 0; s >>= 1) {
        if (threadIdx.x < s) red[threadIdx.x] += red[threadIdx.x + s];
        __syncthreads();
    }
    if (threadIdx.x == 0) g_partials[blk] = red[0];
}

__global__ void finalize_kernel(float* __restrict__ out)
{
    __shared__ float r[NBLOCKS];
    int t = threadIdx.x;
    r[t] = g_partials[t];
    __syncthreads();
    #pragma unroll
    for (int s = NBLOCKS / 2; s > 0; s >>= 1) {
        if (t < s) r[t] += r[t + s];
        __syncthreads();
    }
    // mean_b(mean_n min + mean_m min) = (sum of all 2*B*N mins) / (B*N)  since N==M
    if (t == 0) out[0] = r[0] * (1.0f / (float)(BB * NPTS));
}

extern "C" void kernel_launch(void* const* d_in, const int* in_sizes, int n_in,
                              void* d_out, int out_size)
{
    const float* src = (const float*)d_in[0];
    const float* tgt = (const float*)d_in[1];
    float* out = (float*)d_out;

    const size_t smem_bytes = 2 * NPAIR * sizeof(float4);  // 64 KB
    cudaFuncSetAttribute(chamfer_kernel,
                         cudaFuncAttributeMaxDynamicSharedMemorySize,
                         (int)smem_bytes);

    chamfer_kernel<<<NBLOCKS, TPB, smem_bytes>>>(src, tgt);
    finalize_kernel<<<1, NBLOCKS>>>(out);
}

// round 3
// speedup vs baseline: 1.3817x; 1.3817x over previous
#include <cuda_runtime.h>
#include <cstdint>

#define BB        4
#define NPTS      4096
#define TPB       256
#define QPT       4                      // queries register-cached per thread
#define QPB       (TPB * QPT)            // 1024 queries per block
#define NSLICE    4                      // target slices
#define SLICE_PTS (NPTS / NSLICE)        // 1024 targets per slice
#define SLICE_PR  (SLICE_PTS / 2)        // 512 target pairs in smem (16 KB)
#define NQ_TOTAL  (2 * BB * NPTS)        // 32768 query slots (both directions)
#define NQTILE    (NQ_TOTAL / QPB)       // 32
#define NBLK1     (NQTILE * NSLICE)      // 128 blocks

__device__ float g_min[NSLICE][NQ_TOTAL];

__device__ __forceinline__ uint64_t pk2(float lo, float hi) {
    uint64_t r;
    asm("mov.b64 %0, {%1, %2};" : "=l"(r) : "f"(lo), "f"(hi));
    return r;
}
__device__ __forceinline__ uint64_t fma2(uint64_t a, uint64_t b, uint64_t c) {
    uint64_t d;
    asm("fma.rn.f32x2 %0, %1, %2, %3;" : "=l"(d) : "l"(a), "l"(b), "l"(c));
    return d;
}
__device__ __forceinline__ void unpk(uint64_t v, float& lo, float& hi) {
    asm("mov.b64 {%0, %1}, %2;" : "=f"(lo), "=f"(hi) : "l"(v));
}

// Block = (query-tile of 1024 queries) x (target slice of 1024 points).
// Targets pair-interleaved in smem: sA[p]={x0,x1,y0,y1}, sB[p]={z0,z1,w0,w1}, w=|t|^2.
// Each thread holds 4 queries in registers -> 12 FFMA2 per 2 LDS.128 (FMA-pipe-bound).
__global__ void __launch_bounds__(TPB)
chamfer_stage1(const float* __restrict__ src, const float* __restrict__ tgt)
{
    __shared__ float4 sA[SLICE_PR];
    __shared__ float4 sB[SLICE_PR];

    int qtile = blockIdx.x >> 2;
    int slice = blockIdx.x & 3;
    int dir   = qtile >> 4;              // 0: src->tgt, 1: tgt->src
    int b     = (qtile >> 2) & 3;
    int qsub  = qtile & 3;

    const float* qb = (dir ? tgt : src) + ((size_t)b * NPTS + qsub * QPB) * 3;
    const float* db = (dir ? src : tgt) + ((size_t)b * NPTS + slice * SLICE_PTS) * 3;

    for (int p = threadIdx.x; p < SLICE_PR; p += TPB) {
        const float* t = db + 6 * p;
        float x0 = t[0], y0 = t[1], z0 = t[2];
        float x1 = t[3], y1 = t[4], z1 = t[5];
        sA[p] = make_float4(x0, x1, y0, y1);
        sB[p] = make_float4(z0, z1,
                            fmaf(x0, x0, fmaf(y0, y0, z0 * z0)),
                            fmaf(x1, x1, fmaf(y1, y1, z1 * z1)));
    }

    // Load 4 queries, pre-scale by -2, pack broadcast pairs.
    uint64_t SX[QPT], SY[QPT], SZ[QPT];
    float x2[QPT], m0[QPT], m1[QPT];
    #pragma unroll
    for (int k = 0; k < QPT; k++) {
        int qi = threadIdx.x + k * TPB;
        float sx = qb[3 * qi], sy = qb[3 * qi + 1], sz = qb[3 * qi + 2];
        x2[k] = fmaf(sx, sx, fmaf(sy, sy, sz * sz));
        SX[k] = pk2(-2.f * sx, -2.f * sx);
        SY[k] = pk2(-2.f * sy, -2.f * sy);
        SZ[k] = pk2(-2.f * sz, -2.f * sz);
        m0[k] = 3.4e38f; m1[k] = 3.4e38f;
    }
    __syncthreads();

    const ulonglong2* A  = (const ulonglong2*)sA;   // {x0,x1},{y0,y1}
    const ulonglong2* Bm = (const ulonglong2*)sB;   // {z0,z1},{w0,w1}

    #pragma unroll 4
    for (int p = 0; p < SLICE_PR; p++) {
        ulonglong2 a  = A[p];
        ulonglong2 bb = Bm[p];
        #pragma unroll
        for (int k = 0; k < QPT; k++) {
            uint64_t v = fma2(SX[k], a.x, fma2(SY[k], a.y, fma2(SZ[k], bb.x, bb.y)));
            float v0, v1;
            unpk(v, v0, v1);
            m0[k] = fminf(m0[k], v0);
            m1[k] = fminf(m1[k], v1);
        }
    }

    int gq0 = qtile * QPB + threadIdx.x;
    #pragma unroll
    for (int k = 0; k < QPT; k++)
        g_min[slice][gq0 + k * TPB] = fminf(m0[k], m1[k]) + x2[k];
}

// Single block: min over 4 slices, sum all 32768 query mins, scale.
__global__ void __launch_bounds__(1024)
chamfer_finalize(float* __restrict__ out)
{
    int t = threadIdx.x;
    float sum = 0.f;
    const float4* g0 = (const float4*)g_min[0];
    const float4* g1 = (const float4*)g_min[1];
    const float4* g2 = (const float4*)g_min[2];
    const float4* g3 = (const float4*)g_min[3];

    #pragma unroll
    for (int j = 0; j < NQ_TOTAL / 4 / 1024; j++) {   // 8 iters
        int i = t + j * 1024;
        float4 a = g0[i], b = g1[i], c = g2[i], d = g3[i];
        float mx = fminf(fminf(a.x, b.x), fminf(c.x, d.x));
        float my = fminf(fminf(a.y, b.y), fminf(c.y, d.y));
        float mz = fminf(fminf(a.z, b.z), fminf(c.z, d.z));
        float mw = fminf(fminf(a.w, b.w), fminf(c.w, d.w));
        sum += (mx + my) + (mz + mw);
    }

    #pragma unroll
    for (int off = 16; off > 0; off >>= 1)
        sum += __shfl_down_sync(0xFFFFFFFFu, sum, off);

    __shared__ float ws[32];
    if ((t & 31) == 0) ws[t >> 5] = sum;
    __syncthreads();
    if (t < 32) {
        float s = ws[t];
        #pragma unroll
        for (int off = 16; off > 0; off >>= 1)
            s += __shfl_down_sync(0xFFFFFFFFu, s, off);
        // mean_b(mean_n min_s2t + mean_m min_t2s) = total_sum / (B * NPTS)
        if (t == 0) out[0] = s * (1.0f / (float)(BB * NPTS));
    }
}

extern "C" void kernel_launch(void* const* d_in, const int* in_sizes, int n_in,
                              void* d_out, int out_size)
{
    const float* src = (const float*)d_in[0];
    const float* tgt = (const float*)d_in[1];
    float* out = (float*)d_out;

    chamfer_stage1<<<NBLK1, TPB>>>(src, tgt);
    chamfer_finalize<<<1, 1024>>>(out);
}

// round 4
// speedup vs baseline: 1.5193x; 1.0996x over previous
#include <cuda_runtime.h>
#include <cstdint>

#define BB        4
#define NPTS      4096
#define TPB       512
#define QPT       4                       // queries register-cached per thread
#define QPB       (TPB * QPT)             // 2048 queries per block
#define NSLICE    8                       // target slices
#define SLICE_PTS (NPTS / NSLICE)         // 512 targets per slice
#define SLICE_PR  (SLICE_PTS / 2)         // 256 target pairs in smem (8 KB)
#define NQ_TOTAL  (2 * BB * NPTS)         // 32768 query slots (both directions)
#define NQTILE    (NQ_TOTAL / QPB)        // 16
#define NBLK1     (NQTILE * NSLICE)       // 128 blocks (1 per SM, 16 warps)
#define RTPB      256
#define NBLK2     (NQ_TOTAL / 4 / RTPB)   // 32 reduce blocks, 1 float4/thread

__device__ float g_min[NSLICE][NQ_TOTAL];   // 1 MB, every entry written -> deterministic
__device__ float g_part[NBLK2];
__device__ int   g_ticket;                  // zero-init; last block resets it

__device__ __forceinline__ uint64_t pk2(float lo, float hi) {
    uint64_t r;
    asm("mov.b64 %0, {%1, %2};" : "=l"(r) : "f"(lo), "f"(hi));
    return r;
}
__device__ __forceinline__ uint64_t fma2(uint64_t a, uint64_t b, uint64_t c) {
    uint64_t d;
    asm("fma.rn.f32x2 %0, %1, %2, %3;" : "=l"(d) : "l"(a), "l"(b), "l"(c));
    return d;
}
__device__ __forceinline__ void unpk(uint64_t v, float& lo, float& hi) {
    asm("mov.b64 {%0, %1}, %2;" : "=f"(lo), "=f"(hi) : "l"(v));
}

// Block = (2048-query tile) x (512-target slice). Targets pair-interleaved in smem:
//   sA[p]={x0,x1,y0,y1}  sB[p]={z0,z1,w0,w1}, w=|t|^2.
// Per thread: 4 queries in registers -> per 2-target step: 2 LDS.128 + 12 FFMA2 + 8 FMNMX.
// 4 warps/SMSP hide LDS latency; fma pipe is the binding resource.
__global__ void __launch_bounds__(TPB)
chamfer_stage1(const float* __restrict__ src, const float* __restrict__ tgt)
{
    __shared__ float4 sA[SLICE_PR];
    __shared__ float4 sB[SLICE_PR];

    int qtile = blockIdx.x >> 3;
    int slice = blockIdx.x & 7;
    int dir   = qtile >> 3;               // 0: src->tgt, 1: tgt->src
    int b     = (qtile >> 1) & 3;
    int qsub  = qtile & 1;

    const float* qb = (dir ? tgt : src) + ((size_t)b * NPTS + qsub * QPB) * 3;
    const float* db = (dir ? src : tgt) + ((size_t)b * NPTS + slice * SLICE_PTS) * 3;

    if (threadIdx.x < SLICE_PR) {
        int p = threadIdx.x;
        const float* t = db + 6 * p;
        float x0 = t[0], y0 = t[1], z0 = t[2];
        float x1 = t[3], y1 = t[4], z1 = t[5];
        sA[p] = make_float4(x0, x1, y0, y1);
        sB[p] = make_float4(z0, z1,
                            fmaf(x0, x0, fmaf(y0, y0, z0 * z0)),
                            fmaf(x1, x1, fmaf(y1, y1, z1 * z1)));
    }

    uint64_t SX[QPT], SY[QPT], SZ[QPT];
    float x2[QPT], m0[QPT], m1[QPT];
    #pragma unroll
    for (int k = 0; k < QPT; k++) {
        int qi = threadIdx.x + k * TPB;
        float sx = qb[3 * qi], sy = qb[3 * qi + 1], sz = qb[3 * qi + 2];
        x2[k] = fmaf(sx, sx, fmaf(sy, sy, sz * sz));
        SX[k] = pk2(-2.f * sx, -2.f * sx);
        SY[k] = pk2(-2.f * sy, -2.f * sy);
        SZ[k] = pk2(-2.f * sz, -2.f * sz);
        m0[k] = 3.4e38f; m1[k] = 3.4e38f;
    }
    __syncthreads();

    const ulonglong2* A  = (const ulonglong2*)sA;   // {x0,x1},{y0,y1}
    const ulonglong2* Bm = (const ulonglong2*)sB;   // {z0,z1},{w0,w1}

    #pragma unroll 4
    for (int p = 0; p < SLICE_PR; p++) {
        ulonglong2 a  = A[p];
        ulonglong2 bb = Bm[p];
        #pragma unroll
        for (int k = 0; k < QPT; k++) {
            uint64_t v = fma2(SX[k], a.x, fma2(SY[k], a.y, fma2(SZ[k], bb.x, bb.y)));
            float v0, v1;
            unpk(v, v0, v1);
            m0[k] = fminf(m0[k], v0);
            m1[k] = fminf(m1[k], v1);
        }
    }

    int gq0 = qtile * QPB + threadIdx.x;
    #pragma unroll
    for (int k = 0; k < QPT; k++)
        g_min[slice][gq0 + k * TPB] = fminf(m0[k], m1[k]) + x2[k];
}

// 32 blocks: min over 8 slices + per-block partial sum; last block (ticket)
// sums the 32 partials in fixed order -> deterministic, no extra launch.
__global__ void __launch_bounds__(RTPB)
chamfer_reduce(float* __restrict__ out)
{
    int t   = threadIdx.x;
    int idx = blockIdx.x * RTPB + t;          // float4 index, 4 queries

    float4 m = ((const float4*)g_min[0])[idx];
    #pragma unroll
    for (int s = 1; s < NSLICE; s++) {
        float4 a = ((const float4*)g_min[s])[idx];
        m.x = fminf(m.x, a.x); m.y = fminf(m.y, a.y);
        m.z = fminf(m.z, a.z); m.w = fminf(m.w, a.w);
    }
    float sum = (m.x + m.y) + (m.z + m.w);

    #pragma unroll
    for (int off = 16; off > 0; off >>= 1)
        sum += __shfl_down_sync(0xFFFFFFFFu, sum, off);

    __shared__ float ws[RTPB / 32];
    if ((t & 31) == 0) ws[t >> 5] = sum;
    __syncthreads();
    if (t < 32) {
        float s = (t < RTPB / 32) ? ws[t] : 0.f;
        #pragma unroll
        for (int off = 4; off > 0; off >>= 1)
            s += __shfl_down_sync(0xFFFFFFFFu, s, off);
        if (t == 0) g_part[blockIdx.x] = s;
    }
    __syncthreads();

    __shared__ int amLast;
    if (t == 0) {
        __threadfence();
        int prev = atomicAdd(&g_ticket, 1);
        amLast = (prev == NBLK2 - 1);
    }
    __syncthreads();

    if (amLast && t == 0) {
        float tot = 0.f;
        #pragma unroll
        for (int i = 0; i < NBLK2; i++)
            tot += *((volatile float*)&g_part[i]);   // fixed order -> deterministic
        out[0] = tot * (1.0f / (float)(BB * NPTS));
        g_ticket = 0;                                // reset for next replay
    }
}

extern "C" void kernel_launch(void* const* d_in, const int* in_sizes, int n_in,
                              void* d_out, int out_size)
{
    const float* src = (const float*)d_in[0];
    const float* tgt = (const float*)d_in[1];
    float* out = (float*)d_out;

    chamfer_stage1<<<NBLK1, TPB>>>(src, tgt);
    chamfer_reduce<<<NBLK2, RTPB>>>(out);
}